// round 1
// baseline (speedup 1.0000x reference)
#include <cuda_runtime.h>
#include <math.h>

#define BB 32
#define TT 1024
#define HH 1024
#define W2 2048   // row stride of W (H, 2H)

// Scratch (no cudaMalloc allowed): q projection and pre-softmax energies.
__device__ float g_q[BB * HH];
__device__ float g_energy[BB * TT];

// ---------------------------------------------------------------------------
// Kernel 1: q[b,g] = sum_k hidden[b,k] * W[g,k] + bias[g]   (Wh = W[:, :H])
// One warp per g. grid = (H/8, B), block = 256 (8 warps).
// ---------------------------------------------------------------------------
__global__ void __launch_bounds__(256) qproj_kernel(
    const float* __restrict__ hidden,
    const float* __restrict__ W,
    const float* __restrict__ bias)
{
    const int b    = blockIdx.y;
    const int warp = threadIdx.x >> 5;
    const int lane = threadIdx.x & 31;
    const int g    = blockIdx.x * 8 + warp;

    const float* hrow = hidden + (size_t)b * HH;
    const float* wrow = W + (size_t)g * W2;   // first H cols = Wh[g, :]

    float s = 0.f;
    #pragma unroll 8
    for (int k = lane; k < HH; k += 32)
        s += hrow[k] * wrow[k];

    #pragma unroll
    for (int off = 16; off; off >>= 1)
        s += __shfl_xor_sync(0xffffffffu, s, off);

    if (lane == 0)
        g_q[b * HH + g] = s + bias[g];
}

// ---------------------------------------------------------------------------
// Kernel 2 (main): fused  energy[b,t] = sum_g tanh( enc[b,t,:]·We[g,:] + q[b,g] ) * v[g]
// We[g,h] = W[g*2048 + 1024 + h]  (both operands K-major -> NT gemm)
// Block: 256 threads, tile 128 t x 128 g, K-step 8, 8x8 microtile per thread.
// Loops over the 8 g-tiles internally, accumulating the energy reduction.
// grid = (T/128, B)
// ---------------------------------------------------------------------------
__global__ void __launch_bounds__(256) attn_energy_kernel(
    const float* __restrict__ enc,
    const float* __restrict__ W,
    const float* __restrict__ v)
{
    const int b  = blockIdx.y;
    const int t0 = blockIdx.x * 128;

    __shared__ float As[8][128];   // [k][t]
    __shared__ float Bs[8][128];   // [k][g]
    __shared__ float esm[128];

    const int tid  = threadIdx.x;
    const int tx   = tid & 15;     // g-group (16)
    const int ty   = tid >> 4;     // t-group (16)
    const int lrow = tid >> 1;     // 0..127 : row being loaded
    const int lcol = (tid & 1) * 4;// 0 or 4 : k offset of the float4

    const float* Ab = enc + ((size_t)b * TT + t0) * HH;
    const float* Bb = W + HH;      // We base; row stride W2

    if (tid < 128) esm[tid] = 0.f;

    float eacc[8];
    #pragma unroll
    for (int i = 0; i < 8; i++) eacc[i] = 0.f;

    for (int g0 = 0; g0 < HH; g0 += 128) {
        float c[8][8];
        #pragma unroll
        for (int i = 0; i < 8; i++)
            #pragma unroll
            for (int j = 0; j < 8; j++) c[i][j] = 0.f;

        for (int k0 = 0; k0 < HH; k0 += 8) {
            float4 a4 = *(const float4*)(Ab + (size_t)lrow * HH + k0 + lcol);
            float4 b4 = *(const float4*)(Bb + (size_t)(g0 + lrow) * W2 + k0 + lcol);

            __syncthreads();   // previous iteration's reads done before overwrite
            As[lcol + 0][lrow] = a4.x; As[lcol + 1][lrow] = a4.y;
            As[lcol + 2][lrow] = a4.z; As[lcol + 3][lrow] = a4.w;
            Bs[lcol + 0][lrow] = b4.x; Bs[lcol + 1][lrow] = b4.y;
            Bs[lcol + 2][lrow] = b4.z; Bs[lcol + 3][lrow] = b4.w;
            __syncthreads();

            #pragma unroll
            for (int k = 0; k < 8; k++) {
                float a[8], bb[8];
                *(float4*)(a)      = *(const float4*)&As[k][ty * 8];
                *(float4*)(a + 4)  = *(const float4*)&As[k][ty * 8 + 4];
                *(float4*)(bb)     = *(const float4*)&Bs[k][tx * 8];
                *(float4*)(bb + 4) = *(const float4*)&Bs[k][tx * 8 + 4];
                #pragma unroll
                for (int i = 0; i < 8; i++)
                    #pragma unroll
                    for (int j = 0; j < 8; j++)
                        c[i][j] = fmaf(a[i], bb[j], c[i][j]);
            }
        }

        // Epilogue for this g-tile: tanh(+q) * v, reduce into per-row energy.
        const float* qg = g_q + b * HH + g0 + tx * 8;
        const float* vg = v + g0 + tx * 8;
        #pragma unroll
        for (int j = 0; j < 8; j++) {
            const float qj = qg[j];
            const float vj = vg[j];
            #pragma unroll
            for (int i = 0; i < 8; i++)
                eacc[i] += tanhf(c[i][j] + qj) * vj;
        }
    }

    __syncthreads();
    #pragma unroll
    for (int i = 0; i < 8; i++)
        atomicAdd(&esm[ty * 8 + i], eacc[i]);
    __syncthreads();

    if (tid < 128)
        g_energy[(size_t)b * TT + t0 + tid] = esm[tid];
}

// ---------------------------------------------------------------------------
// Kernel 3: out[b, 0, t] = softmax_t(energy[b, t])   (T = 1024, 256 threads/b)
// ---------------------------------------------------------------------------
__global__ void __launch_bounds__(256) softmax_kernel(float* __restrict__ out)
{
    const int b   = blockIdx.x;
    const int tid = threadIdx.x;
    __shared__ float red[8];
    __shared__ float bc;

    const float* e = g_energy + (size_t)b * TT;

    float loc[4];
    float m = -1e30f;
    #pragma unroll
    for (int i = 0; i < 4; i++) {
        loc[i] = e[tid + i * 256];
        m = fmaxf(m, loc[i]);
    }
    #pragma unroll
    for (int off = 16; off; off >>= 1)
        m = fmaxf(m, __shfl_xor_sync(0xffffffffu, m, off));
    if ((tid & 31) == 0) red[tid >> 5] = m;
    __syncthreads();
    if (tid == 0) {
        float mm = red[0];
        #pragma unroll
        for (int i = 1; i < 8; i++) mm = fmaxf(mm, red[i]);
        bc = mm;
    }
    __syncthreads();
    const float M = bc;

    float s = 0.f;
    #pragma unroll
    for (int i = 0; i < 4; i++) {
        loc[i] = expf(loc[i] - M);
        s += loc[i];
    }
    #pragma unroll
    for (int off = 16; off; off >>= 1)
        s += __shfl_xor_sync(0xffffffffu, s, off);
    if ((tid & 31) == 0) red[tid >> 5] = s;
    __syncthreads();
    if (tid == 0) {
        float ss = 0.f;
        #pragma unroll
        for (int i = 0; i < 8; i++) ss += red[i];
        bc = 1.0f / ss;
    }
    __syncthreads();
    const float inv = bc;

    #pragma unroll
    for (int i = 0; i < 4; i++)
        out[(size_t)b * TT + tid + i * 256] = loc[i] * inv;
}

// ---------------------------------------------------------------------------
extern "C" void kernel_launch(void* const* d_in, const int* in_sizes, int n_in,
                              void* d_out, int out_size)
{
    const float* hidden = (const float*)d_in[0];  // (1, 32, 1024)
    const float* enc    = (const float*)d_in[1];  // (32, 1024, 1024)
    const float* W      = (const float*)d_in[2];  // (1024, 2048)
    const float* bias   = (const float*)d_in[3];  // (1024,)
    const float* v      = (const float*)d_in[4];  // (1024,)
    float* out = (float*)d_out;                   // (32, 1, 1024)

    qproj_kernel<<<dim3(HH / 8, BB), 256>>>(hidden, W, bias);
    attn_energy_kernel<<<dim3(TT / 128, BB), 256>>>(enc, W, v);
    softmax_kernel<<<BB, 256>>>(out);
}

// round 3
// speedup vs baseline: 2.4266x; 2.4266x over previous
#include <cuda_runtime.h>
#include <cuda_bf16.h>
#include <math.h>
#include <stdint.h>

#define BB 32
#define TT 1024
#define HH 1024
#define W2 2048

// ---------------------------------------------------------------------------
// Device scratch (no cudaMalloc allowed)
// ---------------------------------------------------------------------------
__device__ float g_q[BB * HH];
__device__ float g_epart[8][BB][TT];   // partial energies per g-block
__device__ __align__(16) __nv_bfloat16 g_Ahi[(size_t)BB * TT * HH];
__device__ __align__(16) __nv_bfloat16 g_Alo[(size_t)BB * TT * HH];
__device__ __align__(16) __nv_bfloat16 g_Bhi[HH * HH];
__device__ __align__(16) __nv_bfloat16 g_Blo[HH * HH];

// ---------------------------------------------------------------------------
// Helpers
// ---------------------------------------------------------------------------
__device__ __forceinline__ uint32_t smem_to_u32(const void* p) {
    uint32_t a;
    asm("{ .reg .u64 t; cvta.to.shared.u64 t, %1; cvt.u32.u64 %0, t; }" : "=r"(a) : "l"(p));
    return a;
}

#define CP_ASYNC_16(dst, src) \
    asm volatile("cp.async.cg.shared.global [%0], [%1], 16;" :: "r"((uint32_t)(dst)), "l"(src) : "memory")
#define CP_COMMIT() asm volatile("cp.async.commit_group;" ::: "memory")
#define CP_WAIT(n)  asm volatile("cp.async.wait_group %0;" :: "n"(n) : "memory")

#define LDSM4(r, addr) \
    asm volatile("ldmatrix.sync.aligned.m8n8.x4.shared.b16 {%0,%1,%2,%3}, [%4];" \
        : "=r"((r)[0]), "=r"((r)[1]), "=r"((r)[2]), "=r"((r)[3]) : "r"(addr))

#define MMA16816(d, a, b0, b1) \
    asm volatile("mma.sync.aligned.m16n8k16.row.col.f32.bf16.bf16.f32 " \
        "{%0,%1,%2,%3}, {%4,%5,%6,%7}, {%8,%9}, {%0,%1,%2,%3};" \
        : "+f"((d)[0]), "+f"((d)[1]), "+f"((d)[2]), "+f"((d)[3]) \
        : "r"((a)[0]), "r"((a)[1]), "r"((a)[2]), "r"((a)[3]), "r"(b0), "r"(b1))

// FMA-only reciprocal (q > 0): bit-hack seed + 3 Newton steps, rel err ~1e-8
__device__ __forceinline__ float rcp_fma(float q) {
    float y = __uint_as_float(0x7EF311C3u - __float_as_uint(q));
    y = y * fmaf(-q, y, 2.0f);
    y = y * fmaf(-q, y, 2.0f);
    y = y * fmaf(-q, y, 2.0f);
    return y;
}

// FMA-only tanh (XLA 13/6 rational minimax), abs err ~1e-7. NO MUFU.
__device__ __forceinline__ float fast_tanh(float x) {
    float xc = fminf(fmaxf(x, -7.90531f), 7.90531f);
    float x2 = xc * xc;
    float p = -2.76076847742355e-16f;
    p = fmaf(p, x2,  2.00018790482477e-13f);
    p = fmaf(p, x2, -8.60467152213735e-11f);
    p = fmaf(p, x2,  5.12229709037114e-08f);
    p = fmaf(p, x2,  1.48572235717979e-05f);
    p = fmaf(p, x2,  6.37261928875436e-04f);
    p = fmaf(p, x2,  4.89352455891786e-03f);
    p = p * xc;
    float q = 1.19825839466702e-06f;
    q = fmaf(q, x2, 1.18534705686654e-04f);
    q = fmaf(q, x2, 2.26843463243900e-03f);
    q = fmaf(q, x2, 4.89352518554385e-03f);
    return p * rcp_fma(q);
}

// Split 8 consecutive floats into bf16 hi / lo packs
__device__ __forceinline__ void split8(const float* src, uint4& uh, uint4& ul) {
    float4 f0 = *(const float4*)src;
    float4 f1 = *(const float4*)(src + 4);
    float f[8] = {f0.x, f0.y, f0.z, f0.w, f1.x, f1.y, f1.z, f1.w};
    uint32_t h[8], l[8];
    #pragma unroll
    for (int j = 0; j < 8; j++) {
        __nv_bfloat16 hb = __float2bfloat16(f[j]);
        float r = f[j] - __bfloat162float(hb);
        h[j] = (uint32_t)__bfloat16_as_ushort(hb);
        l[j] = (uint32_t)__bfloat16_as_ushort(__float2bfloat16(r));
    }
    uh.x = h[0] | (h[1] << 16); uh.y = h[2] | (h[3] << 16);
    uh.z = h[4] | (h[5] << 16); uh.w = h[6] | (h[7] << 16);
    ul.x = l[0] | (l[1] << 16); ul.y = l[2] | (l[3] << 16);
    ul.z = l[4] | (l[5] << 16); ul.w = l[6] | (l[7] << 16);
}

// ---------------------------------------------------------------------------
// Preconvert kernels
// ---------------------------------------------------------------------------
__global__ void __launch_bounds__(256) convertA_kernel(const float* __restrict__ enc)
{
    size_t i8 = ((size_t)blockIdx.x * 256 + threadIdx.x) * 8;
    uint4 uh, ul;
    split8(enc + i8, uh, ul);
    *(uint4*)&g_Ahi[i8] = uh;
    *(uint4*)&g_Alo[i8] = ul;
}

__global__ void __launch_bounds__(256) convertB_kernel(const float* __restrict__ W)
{
    size_t i8 = ((size_t)blockIdx.x * 256 + threadIdx.x) * 8;
    size_t g = i8 >> 10, h = i8 & 1023;
    float f[8];
    const float* src = W + g * W2 + HH + h;
    uint4 uh, ul;
    split8(src, uh, ul);
    *(uint4*)&g_Bhi[i8] = uh;
    *(uint4*)&g_Blo[i8] = ul;
    (void)f;
}

// ---------------------------------------------------------------------------
// q[b,g] = hidden[b,:] . Wh[g,:] + bias[g]
// ---------------------------------------------------------------------------
__global__ void __launch_bounds__(256) qproj_kernel(
    const float* __restrict__ hidden, const float* __restrict__ W, const float* __restrict__ bias)
{
    const int warp = threadIdx.x >> 5, lane = threadIdx.x & 31;
    const int g = blockIdx.x * 8 + warp;
    const float* wrow = W + (size_t)g * W2;
    float wreg[32];
    #pragma unroll
    for (int i = 0; i < 32; i++) wreg[i] = wrow[lane + 32 * i];
    const float bg = bias[g];
    for (int b = 0; b < BB; b++) {
        const float* h = hidden + (size_t)b * HH;
        float s = 0.f;
        #pragma unroll
        for (int i = 0; i < 32; i++) s += wreg[i] * h[lane + 32 * i];
        #pragma unroll
        for (int off = 16; off; off >>= 1) s += __shfl_xor_sync(0xffffffffu, s, off);
        if (lane == 0) g_q[b * HH + g] = s + bg;
    }
}

// ---------------------------------------------------------------------------
// Main kernel: split-bf16 mma.sync GEMM (BM=128 t, BN=128 g, BK=32) + fused
// tanh/v epilogue. grid = (8, 8, 32), block = 256 (8 warps, 4x2 warp grid).
// ---------------------------------------------------------------------------
#define SROW 80                         // bytes per smem row (32 bf16 + 8 pad)
#define OFFA_HI 0
#define OFFA_LO (128 * SROW)            // 10240
#define OFFB_HI (2 * 128 * SROW)        // 20480
#define OFFB_LO (3 * 128 * SROW)        // 30720
#define STAGE_BYTES (4 * 128 * SROW)    // 40960
#define SMEM_BYTES (2 * STAGE_BYTES)    // 81920

__global__ void __launch_bounds__(256, 2) energy_kernel(const float* __restrict__ v)
{
    extern __shared__ char smem[];
    const uint32_t sb = smem_to_u32(smem);
    __shared__ float esm[128];

    const int tid = threadIdx.x;
    const int lane = tid & 31, wid = tid >> 5;
    const int warp_m = wid & 3, warp_n = wid >> 2;
    const int t0 = blockIdx.x * 128, g0 = blockIdx.y * 128, b = blockIdx.z;

    if (tid < 128) esm[tid] = 0.f;

    // Loader setup: thread -> (row, two 16B chunks)
    const int lrow = tid >> 1;
    const int cb = (tid & 1) * 2;             // chunk base 0 or 2 (16B chunks)
    const __nv_bfloat16* pAh = g_Ahi + ((size_t)(b * TT + t0 + lrow)) * HH + cb * 8;
    const __nv_bfloat16* pAl = g_Alo + ((size_t)(b * TT + t0 + lrow)) * HH + cb * 8;
    const __nv_bfloat16* pBh = g_Bhi + ((size_t)(g0 + lrow)) * HH + cb * 8;
    const __nv_bfloat16* pBl = g_Blo + ((size_t)(g0 + lrow)) * HH + cb * 8;
    const uint32_t sdst = (uint32_t)lrow * SROW + (uint32_t)cb * 16;

    float acc[2][8][4];
    #pragma unroll
    for (int i = 0; i < 2; i++)
        #pragma unroll
        for (int j = 0; j < 8; j++)
            #pragma unroll
            for (int k = 0; k < 4; k++) acc[i][j][k] = 0.f;

    // ldmatrix address components
    const uint32_t lr15 = (uint32_t)(lane & 15);
    const uint32_t lk16 = (uint32_t)(lane >> 4) * 16;   // bytes

    // ---- pipeline ----
    #define LOAD_STAGE(buf, kc) do { \
        const uint32_t s_ = sb + (buf) * STAGE_BYTES + sdst; \
        const int ko_ = (kc) * 32; \
        CP_ASYNC_16(s_ + OFFA_HI,      pAh + ko_); \
        CP_ASYNC_16(s_ + OFFA_HI + 16, pAh + ko_ + 8); \
        CP_ASYNC_16(s_ + OFFA_LO,      pAl + ko_); \
        CP_ASYNC_16(s_ + OFFA_LO + 16, pAl + ko_ + 8); \
        CP_ASYNC_16(s_ + OFFB_HI,      pBh + ko_); \
        CP_ASYNC_16(s_ + OFFB_HI + 16, pBh + ko_ + 8); \
        CP_ASYNC_16(s_ + OFFB_LO,      pBl + ko_); \
        CP_ASYNC_16(s_ + OFFB_LO + 16, pBl + ko_ + 8); \
    } while (0)

    LOAD_STAGE(0, 0);
    CP_COMMIT();

    for (int kc = 0; kc < 32; kc++) {
        if (kc < 31) {
            LOAD_STAGE((kc + 1) & 1, kc + 1);
            CP_COMMIT();
            CP_WAIT(1);
        } else {
            CP_WAIT(0);
        }
        __syncthreads();

        const uint32_t sbase = sb + (kc & 1) * STAGE_BYTES;
        #pragma unroll
        for (int s = 0; s < 2; s++) {
            const uint32_t koff = (uint32_t)s * 32 + lk16;
            const uint32_t arow = (uint32_t)(warp_m * 32) * SROW + lr15 * SROW;
            uint32_t ah[2][4], al[2][4];
            LDSM4(ah[0], sbase + OFFA_HI + arow + koff);
            LDSM4(ah[1], sbase + OFFA_HI + arow + 16 * SROW + koff);
            LDSM4(al[0], sbase + OFFA_LO + arow + koff);
            LDSM4(al[1], sbase + OFFA_LO + arow + 16 * SROW + koff);
            #pragma unroll
            for (int np = 0; np < 4; np++) {
                const uint32_t brow = (uint32_t)(warp_n * 64 + np * 16) * SROW + lr15 * SROW;
                uint32_t bh[4], bl[4];
                LDSM4(bh, sbase + OFFB_HI + brow + koff);
                LDSM4(bl, sbase + OFFB_LO + brow + koff);
                #pragma unroll
                for (int mt = 0; mt < 2; mt++) {
                    MMA16816(acc[mt][np * 2 + 0], ah[mt], bh[0], bh[2]);
                    MMA16816(acc[mt][np * 2 + 1], ah[mt], bh[1], bh[3]);
                    MMA16816(acc[mt][np * 2 + 0], ah[mt], bl[0], bl[2]);
                    MMA16816(acc[mt][np * 2 + 1], ah[mt], bl[1], bl[3]);
                    MMA16816(acc[mt][np * 2 + 0], al[mt], bh[0], bh[2]);
                    MMA16816(acc[mt][np * 2 + 1], al[mt], bh[1], bh[3]);
                }
            }
        }
        __syncthreads();
    }

    // ---- epilogue: tanh(acc + q) * v, reduce per t-row ----
    const float* qrow = g_q + b * HH + g0 + warp_n * 64;
    const float* vrow = v + g0 + warp_n * 64;
    float part[2][2] = {{0.f, 0.f}, {0.f, 0.f}};
    #pragma unroll
    for (int np = 0; np < 4; np++) {
        #pragma unroll
        for (int nt = 0; nt < 2; nt++) {
            const int gl = np * 16 + nt * 8 + (lane & 3) * 2;
            const float2 q2 = *(const float2*)(qrow + gl);
            const float2 v2 = *(const float2*)(vrow + gl);
            #pragma unroll
            for (int mt = 0; mt < 2; mt++) {
                const float* c = acc[mt][np * 2 + nt];
                #pragma unroll
                for (int rh = 0; rh < 2; rh++) {
                    part[mt][rh] += fast_tanh(c[rh * 2 + 0] + q2.x) * v2.x
                                  + fast_tanh(c[rh * 2 + 1] + q2.y) * v2.y;
                }
            }
        }
    }
    #pragma unroll
    for (int mt = 0; mt < 2; mt++) {
        #pragma unroll
        for (int rh = 0; rh < 2; rh++) {
            float p = part[mt][rh];
            p += __shfl_xor_sync(0xffffffffu, p, 1);
            p += __shfl_xor_sync(0xffffffffu, p, 2);
            if ((lane & 3) == 0)
                atomicAdd(&esm[warp_m * 32 + mt * 16 + rh * 8 + (lane >> 2)], p);
        }
    }
    __syncthreads();
    if (tid < 128)
        g_epart[blockIdx.y][b][t0 + tid] = esm[tid];
}

// ---------------------------------------------------------------------------
// Softmax over t (sums the 8 partial g-block slices deterministically)
// ---------------------------------------------------------------------------
__global__ void __launch_bounds__(256) softmax_kernel(float* __restrict__ out)
{
    const int b = blockIdx.x;
    const int tid = threadIdx.x;
    __shared__ float red[8];
    __shared__ float bc;

    float loc[4];
    float m = -1e30f;
    #pragma unroll
    for (int i = 0; i < 4; i++) {
        int t = tid + i * 256;
        float s = 0.f;
        #pragma unroll
        for (int sl = 0; sl < 8; sl++) s += g_epart[sl][b][t];
        loc[i] = s;
        m = fmaxf(m, s);
    }
    #pragma unroll
    for (int off = 16; off; off >>= 1) m = fmaxf(m, __shfl_xor_sync(0xffffffffu, m, off));
    if ((tid & 31) == 0) red[tid >> 5] = m;
    __syncthreads();
    if (tid == 0) {
        float mm = red[0];
        #pragma unroll
        for (int i = 1; i < 8; i++) mm = fmaxf(mm, red[i]);
        bc = mm;
    }
    __syncthreads();
    const float M = bc;

    float s = 0.f;
    #pragma unroll
    for (int i = 0; i < 4; i++) {
        loc[i] = expf(loc[i] - M);
        s += loc[i];
    }
    #pragma unroll
    for (int off = 16; off; off >>= 1) s += __shfl_xor_sync(0xffffffffu, s, off);
    if ((tid & 31) == 0) red[tid >> 5] = s;
    __syncthreads();
    if (tid == 0) {
        float ss = 0.f;
        #pragma unroll
        for (int i = 0; i < 8; i++) ss += red[i];
        bc = 1.0f / ss;
    }
    __syncthreads();
    const float inv = bc;
    #pragma unroll
    for (int i = 0; i < 4; i++)
        out[(size_t)b * TT + tid + i * 256] = loc[i] * inv;
}

// ---------------------------------------------------------------------------
extern "C" void kernel_launch(void* const* d_in, const int* in_sizes, int n_in,
                              void* d_out, int out_size)
{
    const float* hidden = (const float*)d_in[0];  // (1, 32, 1024)
    const float* enc    = (const float*)d_in[1];  // (32, 1024, 1024)
    const float* W      = (const float*)d_in[2];  // (1024, 2048)
    const float* bias   = (const float*)d_in[3];  // (1024,)
    const float* v      = (const float*)d_in[4];  // (1024,)
    float* out = (float*)d_out;                   // (32, 1, 1024)

    cudaFuncSetAttribute(energy_kernel,
                         cudaFuncAttributeMaxDynamicSharedMemorySize, SMEM_BYTES);

    convertA_kernel<<<(BB * TT * HH) / (256 * 8), 256>>>(enc);
    convertB_kernel<<<(HH * HH) / (256 * 8), 256>>>(W);
    qproj_kernel<<<HH / 8, 256>>>(hidden, W, bias);
    energy_kernel<<<dim3(TT / 128, HH / 128, BB), 256, SMEM_BYTES>>>(v);
    softmax_kernel<<<BB, 256>>>(out);
}